// round 14
// baseline (speedup 1.0000x reference)
#include <cuda_runtime.h>

// SKA: out[b, g*8+cw, h, w] = sum_{i,j} x[b, g*8+cw, h+i-1, w+j-1] * w[b, cw, i*3+j, h, w]
// x: (8,64,128,128) f32, w: (8,8,9,128,128) f32, out: (8,64,128,128) f32
//
// R14: occupancy experiment with a clean (pure-LDG, register-weight) body.
// Evidence: prefetch warmed L2 earlier and changed nothing -> hot loads were
// already L2 hits; binder = per-warp L2-hit-latency (~250cyc) chains at only
// 28 warps/SM. Fix: float2 lanes (warp covers 64 cols, block's 8 warps = 8 cw,
// grid (h,side)x(b)) halves weight regs 36->18 => ~48 regs =>
// __launch_bounds__(256,5) -> 40 warps/SM, no smem, no shuffles, no MIO load.

#define SKA_H 128
#define SKA_W 128
#define SKA_C 64
#define SKA_CW 8
#define SKA_HW (SKA_H * SKA_W)

__global__ __launch_bounds__(256, 5)
void SKA_44830868635847_kernel(const float* __restrict__ x,
                               const float* __restrict__ wgt,
                               float* __restrict__ out) {
    const int tid  = threadIdx.x;
    const int lane = tid & 31;
    const int cw   = tid >> 5;             // 0..7: one warp per weight channel
    const int h    = blockIdx.x >> 1;      // 0..127
    const int side = blockIdx.x & 1;       // 0..1: left/right 64-col half
    const int b    = blockIdx.y;           // 0..7
    const int w0   = side * 64 + lane * 2; // 0,2,...,126

    const float* xb = x + (long)(b * SKA_C) * SKA_HW;
    float* ob = out + (long)(b * SKA_C) * SKA_HW;

    // 9 per-position weight pairs for (b, cw, h, w0..w0+1), registers,
    // reused across all 8 group channels.
    float2 wv[9];
    const float* wp = wgt + ((long)(b * SKA_CW + cw) * 9 * SKA_H + h) * SKA_W + w0;
    #pragma unroll
    for (int k = 0; k < 9; k++) {
        wv[k] = *reinterpret_cast<const float2*>(wp + (long)k * SKA_HW);
    }

    #pragma unroll
    for (int g = 0; g < 8; g++) {
        const int c = g * SKA_CW + cw;
        const float* xc = xb + (long)c * SKA_HW;

        float acc0 = 0.f, acc1 = 0.f;

        #pragma unroll
        for (int i = 0; i < 3; i++) {
            const int hh = h + i - 1;
            // r[t] = x[c, hh, w0 + t - 1], t = 0..3; zeros at borders
            float r0, r1, r2, r3;
            if (hh < 0 || hh >= SKA_H) {               // warp-uniform branch
                r0 = r1 = r2 = r3 = 0.f;
            } else {
                const float* row = xc + hh * SKA_W + w0;
                const float2 m = *reinterpret_cast<const float2*>(row);
                r1 = m.x; r2 = m.y;
                r0 = (w0 == 0)            ? 0.f : row[-1];
                r3 = (w0 + 2 >= SKA_W)    ? 0.f : row[2];
            }
            {
                const float2 wk = wv[i * 3 + 0];       // j=0
                acc0 = fmaf(wk.x, r0, acc0);
                acc1 = fmaf(wk.y, r1, acc1);
            }
            {
                const float2 wk = wv[i * 3 + 1];       // j=1
                acc0 = fmaf(wk.x, r1, acc0);
                acc1 = fmaf(wk.y, r2, acc1);
            }
            {
                const float2 wk = wv[i * 3 + 2];       // j=2
                acc0 = fmaf(wk.x, r2, acc0);
                acc1 = fmaf(wk.y, r3, acc1);
            }
        }

        float2 o; o.x = acc0; o.y = acc1;
        *reinterpret_cast<float2*>(ob + (long)c * SKA_HW + h * SKA_W + w0) = o;
    }
}

extern "C" void kernel_launch(void* const* d_in, const int* in_sizes, int n_in,
                              void* d_out, int out_size) {
    const float* x = (const float*)d_in[0];
    const float* w = (const float*)d_in[1];
    float* out = (float*)d_out;
    (void)in_sizes; (void)n_in; (void)out_size;

    dim3 grid(SKA_H * 2, 8);   // (h, side) x b : 2048 blocks
    dim3 block(256);           // 8 warps = 8 cw; lane covers 2 columns
    SKA_44830868635847_kernel<<<grid, block>>>(x, w, out);
}

// round 15
// speedup vs baseline: 1.7838x; 1.7838x over previous
#include <cuda_runtime.h>

// SKA: out[b, g*8+cw, h, w] = sum_{i,j} x[b, g*8+cw, h+i-1, w+j-1] * w[b, cw, i*3+j, h, w]
// x: (8,64,128,128) f32, w: (8,8,9,128,128) f32, out: (8,64,128,128) f32
//
// R15 = R5 body (best kernel: 25.9us) + streaming output stores (__stcs).
// Model surviving 7 experiments: dur ~ (# DRAM transactions) / const-rate;
// occupancy/ILP/prefetch all neutral because they don't change miss count.
// The 33.5MB write-only output stream thrashes L2 and evicts x+w (71MB,
// which would otherwise fit in the 126MB L2 across graph replays), causing
// ~43MB of avoidable read misses per launch. st.global.cs (evict-first)
// keeps the output stream out of L2's working set -> DRAM traffic ~77->~40MB.

#define SKA_H 128
#define SKA_W 128
#define SKA_C 64
#define SKA_CW 8
#define SKA_HW (SKA_H * SKA_W)

__global__ __launch_bounds__(128, 8)
void SKA_44830868635847_kernel(const float* __restrict__ x,
                               const float* __restrict__ wgt,
                               float* __restrict__ out) {
    const int tid  = threadIdx.x;
    const int lane = tid & 31;
    const int w0   = lane << 2;    // 0,4,...,124 (warp spans the full row)
    const int wid  = tid >> 5;     // 0..3
    const int h    = blockIdx.x;   // 0..127
    const int b    = blockIdx.y;   // 0..7

    const float* xb = x + (long)(b * SKA_C) * SKA_HW;
    float* ob = out + (long)(b * SKA_C) * SKA_HW;

    #pragma unroll 1
    for (int half = 0; half < 2; half++) {
        const int cw = wid + half * 4;   // weight channel for this pass

        // 9 per-position weight vectors, in registers, reused across 8 channels.
        float4 wv[9];
        const float* wp = wgt + ((long)(b * SKA_CW + cw) * 9 * SKA_H + h) * SKA_W + w0;
        #pragma unroll
        for (int k = 0; k < 9; k++) {
            wv[k] = *reinterpret_cast<const float4*>(wp + (long)k * SKA_HW);
        }

        #pragma unroll
        for (int g = 0; g < 8; g++) {
            const int c = g * SKA_CW + cw;
            const float* xc = xb + (long)c * SKA_HW;

            float acc0 = 0.f, acc1 = 0.f, acc2 = 0.f, acc3 = 0.f;

            #pragma unroll
            for (int i = 0; i < 3; i++) {
                const int hh = h + i - 1;
                float r0, r1, r2, r3, r4, r5;
                if (hh < 0 || hh >= SKA_H) {           // warp-uniform
                    r0 = r1 = r2 = r3 = r4 = r5 = 0.f;
                } else {
                    const float* row = xc + hh * SKA_W + w0;
                    const float4 m = *reinterpret_cast<const float4*>(row);
                    r1 = m.x; r2 = m.y; r3 = m.z; r4 = m.w;
                    r0 = (w0 == 0)         ? 0.f : row[-1];
                    r5 = (w0 + 4 >= SKA_W) ? 0.f : row[4];
                }
                {
                    const float4 wk = wv[i * 3 + 0];   // j=0
                    acc0 = fmaf(wk.x, r0, acc0);
                    acc1 = fmaf(wk.y, r1, acc1);
                    acc2 = fmaf(wk.z, r2, acc2);
                    acc3 = fmaf(wk.w, r3, acc3);
                }
                {
                    const float4 wk = wv[i * 3 + 1];   // j=1
                    acc0 = fmaf(wk.x, r1, acc0);
                    acc1 = fmaf(wk.y, r2, acc1);
                    acc2 = fmaf(wk.z, r3, acc2);
                    acc3 = fmaf(wk.w, r4, acc3);
                }
                {
                    const float4 wk = wv[i * 3 + 2];   // j=2
                    acc0 = fmaf(wk.x, r2, acc0);
                    acc1 = fmaf(wk.y, r3, acc1);
                    acc2 = fmaf(wk.z, r4, acc2);
                    acc3 = fmaf(wk.w, r5, acc3);
                }
            }

            float4 o;
            o.x = acc0; o.y = acc1; o.z = acc2; o.w = acc3;
            // streaming store: evict-first, keep the write stream out of L2's
            // useful working set (out is write-only)
            __stcs(reinterpret_cast<float4*>(ob + (long)c * SKA_HW + h * SKA_W + w0), o);
        }
    }
}

extern "C" void kernel_launch(void* const* d_in, const int* in_sizes, int n_in,
                              void* d_out, int out_size) {
    const float* x = (const float*)d_in[0];
    const float* w = (const float*)d_in[1];
    float* out = (float*)d_out;
    (void)in_sizes; (void)n_in; (void)out_size;

    dim3 grid(SKA_H, 8);   // (h, b): 1024 blocks
    dim3 block(128);       // 4 warps; each warp covers cw=wid and wid+4
    SKA_44830868635847_kernel<<<grid, block>>>(x, w, out);
}